// round 3
// baseline (speedup 1.0000x reference)
#include <cuda_runtime.h>
#include <math.h>

#define BB 8
#define HW 1024
#define CCH 256
#define CATC 1024

// ---------------- scratch (no allocations allowed) ----------------
__device__ float g_cat[BB * CATC * HW];        // 32 MB concat buffer [b][1024][1024]
__device__ float g_z[BB * CCH * HW];           // 3x3 conv output
__device__ float g_qkv[BB * 3 * CCH * HW];     // qkv conv output
__device__ float g_att[BB * CCH * HW];         // attention output
__device__ float g_scale[2048];                // folded BN scale
__device__ float g_shift[2048];                // folded BN shift
// scale/shift offsets: cv1=0(512), cv2=512(512), mcv1=1024(+i*256), mcv2=1536(+i*256)

__device__ __forceinline__ float silu_f(float x) { return x / (1.f + __expf(-x)); }

// ---------------- BN fold ----------------
__global__ void bn_prep(const float* __restrict__ cv1, const float* __restrict__ cv2,
                        const float* __restrict__ m1, const float* __restrict__ m2) {
    int tid = blockIdx.x * 256 + threadIdx.x;
    if (tid >= 2048) return;
    const float* p; int c; int cc;
    if (tid < 512)       { p = cv1; c = tid;        cc = 512; }
    else if (tid < 1024) { p = cv2; c = tid - 512;  cc = 512; }
    else if (tid < 1536) { int j = tid - 1024; p = m1 + (j >> 8) * 1024; c = j & 255; cc = 256; }
    else                 { int j = tid - 1536; p = m2 + (j >> 8) * 1024; c = j & 255; cc = 256; }
    float g = p[c], bb = p[cc + c], mm = p[2 * cc + c], vv = p[3 * cc + c];
    float s = g * rsqrtf(vv + 1e-3f);
    g_scale[tid] = s;
    g_shift[tid] = bb - mm * s;
}

// ---------------- 1x1 conv as per-batch GEMM ----------------
// EPI 0: BN+SiLU   EPI 1: BN+SiLU+residual   EPI 2: qkv epilogue (q*=0.125, k+=rw+rh)
template <int EPI>
__global__ void gemm1x1(const float* __restrict__ X, long xBS,
                        const float* __restrict__ W, int Cin,
                        float* __restrict__ out, long outBS, int coOff,
                        const float* __restrict__ scale, const float* __restrict__ shift,
                        const float* __restrict__ res, long resBS,
                        const float* __restrict__ rw, const float* __restrict__ rh) {
    __shared__ float Xs[16][128];
    __shared__ float Ws[16][64];
    int t = threadIdx.x;
    int m0 = blockIdx.x * 128, n0 = blockIdx.y * 64, b = blockIdx.z;
    const float* Xb = X + (long)b * xBS + m0;
    float acc[8][4];
#pragma unroll
    for (int u = 0; u < 8; u++)
#pragma unroll
        for (int v = 0; v < 4; v++) acc[u][v] = 0.f;
    int tm = (t & 15) * 8, tn = (t >> 4) * 4;

    for (int k0 = 0; k0 < Cin; k0 += 16) {
#pragma unroll
        for (int p = 0; p < 2; p++) {
            int id = p * 256 + t, kk = id >> 5, m4 = (id & 31) * 4;
            *(float4*)&Xs[kk][m4] = *(const float4*)&Xb[(long)(k0 + kk) * HW + m4];
        }
        {
            int n = t >> 2, kk = (t & 3) * 4;
            float4 w4 = *(const float4*)&W[(long)(n0 + n) * Cin + k0 + kk];
            Ws[kk][n] = w4.x; Ws[kk + 1][n] = w4.y; Ws[kk + 2][n] = w4.z; Ws[kk + 3][n] = w4.w;
        }
        __syncthreads();
#pragma unroll
        for (int kk = 0; kk < 16; kk++) {
            float4 x0 = *(const float4*)&Xs[kk][tm];
            float4 x1 = *(const float4*)&Xs[kk][tm + 4];
            float4 w4 = *(const float4*)&Ws[kk][tn];
            float xv[8] = {x0.x, x0.y, x0.z, x0.w, x1.x, x1.y, x1.z, x1.w};
            float wv[4] = {w4.x, w4.y, w4.z, w4.w};
#pragma unroll
            for (int u = 0; u < 8; u++)
#pragma unroll
                for (int v = 0; v < 4; v++) acc[u][v] = fmaf(xv[u], wv[v], acc[u][v]);
        }
        __syncthreads();
    }

#pragma unroll
    for (int v = 0; v < 4; v++) {
        int co = n0 + tn + v;
        float s = 0.f, sh = 0.f;
        if (EPI < 2) { s = scale[co]; sh = shift[co]; }
        float* op = out + (long)b * outBS + (long)(coOff + co) * HW + m0 + tm;
        const float* rp = (EPI == 1) ? res + (long)b * resBS + (long)co * HW + m0 + tm : nullptr;
#pragma unroll
        for (int g2 = 0; g2 < 2; g2++) {
            float4 r; float* rr = &r.x;
#pragma unroll
            for (int e = 0; e < 4; e++) {
                int u = g2 * 4 + e;
                float val = acc[u][v];
                if (EPI < 2) {
                    val = silu_f(val * s + sh);
                    if (EPI == 1) val += rp[u];
                } else {
                    int m = m0 + tm + u;
                    int part = co >> 8, cr = co & 255;
                    if (part == 0) val *= 0.125f;
                    else if (part == 1) val += rw[cr * 32 + (m & 31)] + rh[cr * 32 + (m >> 5)];
                }
                rr[e] = val;
            }
            *(float4*)&op[g2 * 4] = r;
        }
    }
}

// ---------------- 3x3 conv, implicit GEMM (K = 256*9 = 2304) ----------------
__global__ void conv3x3(const float* __restrict__ X, long xBS,
                        const float* __restrict__ W,
                        float* __restrict__ out,
                        const float* __restrict__ scale, const float* __restrict__ shift) {
    __shared__ float Xs[16][128];
    __shared__ float Ws[16][64];
    int t = threadIdx.x;
    int m0 = blockIdx.x * 128, n0 = blockIdx.y * 64, b = blockIdx.z;
    const float* Xb = X + (long)b * xBS;
    float acc[8][4];
#pragma unroll
    for (int u = 0; u < 8; u++)
#pragma unroll
        for (int v = 0; v < 4; v++) acc[u][v] = 0.f;
    int tm = (t & 15) * 8, tn = (t >> 4) * 4;

    for (int k0 = 0; k0 < 2304; k0 += 16) {
#pragma unroll
        for (int p = 0; p < 8; p++) {
            int id = p * 256 + t, kk = id >> 7, mm = id & 127;
            int kg = k0 + kk;
            int ci = kg / 9, rs = kg - ci * 9;
            int r3 = rs / 3;
            int dr = r3 - 1, ds = rs - r3 * 3 - 1;
            int m = m0 + mm;
            int hh = (m >> 5) + dr, ww = (m & 31) + ds;
            float v = 0.f;
            if ((unsigned)hh < 32u && (unsigned)ww < 32u)
                v = Xb[(long)ci * HW + hh * 32 + ww];
            Xs[kk][mm] = v;
        }
        {
            int n = t >> 2, kk = (t & 3) * 4;
            float4 w4 = *(const float4*)&W[(long)(n0 + n) * 2304 + k0 + kk];
            Ws[kk][n] = w4.x; Ws[kk + 1][n] = w4.y; Ws[kk + 2][n] = w4.z; Ws[kk + 3][n] = w4.w;
        }
        __syncthreads();
#pragma unroll
        for (int kk = 0; kk < 16; kk++) {
            float4 x0 = *(const float4*)&Xs[kk][tm];
            float4 x1 = *(const float4*)&Xs[kk][tm + 4];
            float4 w4 = *(const float4*)&Ws[kk][tn];
            float xv[8] = {x0.x, x0.y, x0.z, x0.w, x1.x, x1.y, x1.z, x1.w};
            float wv[4] = {w4.x, w4.y, w4.z, w4.w};
#pragma unroll
            for (int u = 0; u < 8; u++)
#pragma unroll
                for (int v = 0; v < 4; v++) acc[u][v] = fmaf(xv[u], wv[v], acc[u][v]);
        }
        __syncthreads();
    }

#pragma unroll
    for (int v = 0; v < 4; v++) {
        int co = n0 + tn + v;
        float s = scale[co], sh = shift[co];
        float* op = out + ((long)b * 256 + co) * HW + m0 + tm;
#pragma unroll
        for (int g2 = 0; g2 < 2; g2++) {
            float4 r; float* rr = &r.x;
#pragma unroll
            for (int e = 0; e < 4; e++) rr[e] = silu_f(acc[g2 * 4 + e][v] * s + sh);
            *(float4*)&op[g2 * 4] = r;
        }
    }
}

// ---------------- attention ----------------
// grid (32 i-tiles, 32 b*h); block 256; dynamic smem 157824 B
// S stored transposed St[j][i] (stride 32) so AV phase is float4-friendly.
#define KVR 68
__device__ __forceinline__ void fma4(float4& o, float4 v, float4 s0, float4 s1, float4 s2, float4 s3) {
    o.x = fmaf(v.x, s0.x, fmaf(v.y, s1.x, fmaf(v.z, s2.x, fmaf(v.w, s3.x, o.x))));
    o.y = fmaf(v.x, s0.y, fmaf(v.y, s1.y, fmaf(v.z, s2.y, fmaf(v.w, s3.y, o.y))));
    o.z = fmaf(v.x, s0.z, fmaf(v.y, s1.z, fmaf(v.z, s2.z, fmaf(v.w, s3.z, o.z))));
    o.w = fmaf(v.x, s0.w, fmaf(v.y, s1.w, fmaf(v.z, s2.w, fmaf(v.w, s3.w, o.w))));
}

__global__ void attn_kernel(const float* __restrict__ qkv, float* __restrict__ out) {
    extern __shared__ float sm[];
    float* St   = sm;              // [1024][32]
    float* Qs   = St + 1024 * 32;  // [64][32]
    float* KV   = Qs + 2048;       // [64][KVR]
    float* red  = KV + 64 * KVR;   // [8][32]
    float* rsum = red + 256;       // [32]

    int t = threadIdx.x;
    int b = blockIdx.y >> 2, h = blockIdx.y & 3;
    int i0 = blockIdx.x * 32;
    const float* qb = qkv + ((long)b * 768 + h * 64) * HW;
    const float* kb = qb + 256 * HW;
    const float* vb = qb + 512 * HW;

    // load Q tile [64 d][32 i]
#pragma unroll
    for (int p = 0; p < 2; p++) {
        int id = p * 256 + t, d = id >> 3, i4 = (id & 7) * 4;
        *(float4*)&Qs[d * 32 + i4] = *(const float4*)&qb[(long)d * HW + i0 + i4];
    }

    // phase 1: S = Q^T K'  -> St[j][i]
    int is = t & 15, js = t >> 4;
    int ii0 = is * 2, jj0 = js * 4;
    for (int jt = 0; jt < 16; jt++) {
        __syncthreads();
#pragma unroll
        for (int p = 0; p < 4; p++) {
            int id = p * 256 + t, d = id >> 4, j4 = (id & 15) * 4;
            *(float4*)&KV[d * KVR + j4] = *(const float4*)&kb[(long)d * HW + jt * 64 + j4];
        }
        __syncthreads();
        float a0x = 0, a0y = 0, a0z = 0, a0w = 0, a1x = 0, a1y = 0, a1z = 0, a1w = 0;
#pragma unroll
        for (int d = 0; d < 64; d++) {
            float2 q = *(const float2*)&Qs[d * 32 + ii0];
            float4 k4 = *(const float4*)&KV[d * KVR + jj0];
            a0x = fmaf(q.x, k4.x, a0x); a0y = fmaf(q.x, k4.y, a0y);
            a0z = fmaf(q.x, k4.z, a0z); a0w = fmaf(q.x, k4.w, a0w);
            a1x = fmaf(q.y, k4.x, a1x); a1y = fmaf(q.y, k4.y, a1y);
            a1z = fmaf(q.y, k4.z, a1z); a1w = fmaf(q.y, k4.w, a1w);
        }
        int jb = jt * 64 + jj0;
        *(float2*)&St[(jb + 0) * 32 + ii0] = make_float2(a0x, a1x);
        *(float2*)&St[(jb + 1) * 32 + ii0] = make_float2(a0y, a1y);
        *(float2*)&St[(jb + 2) * 32 + ii0] = make_float2(a0z, a1z);
        *(float2*)&St[(jb + 3) * 32 + ii0] = make_float2(a0w, a1w);
    }
    __syncthreads();

    // phase 2: softmax over j per column i  (warp w handles j = w mod 8)
    {
        int i = t & 31, w = t >> 5;
        float mx = -1e30f;
        for (int j = w; j < 1024; j += 8) mx = fmaxf(mx, St[j * 32 + i]);
        red[w * 32 + i] = mx;
        __syncthreads();
        mx = red[i];
#pragma unroll
        for (int u = 1; u < 8; u++) mx = fmaxf(mx, red[u * 32 + i]);
        __syncthreads();                 // all reads of red done before reuse
        float s = 0.f;
        for (int j = w; j < 1024; j += 8) {
            float e = __expf(St[j * 32 + i] - mx);
            St[j * 32 + i] = e;
            s += e;
        }
        red[w * 32 + i] = s;
        __syncthreads();
        float tot = 0.f;
#pragma unroll
        for (int u = 0; u < 8; u++) tot += red[u * 32 + i];
        if (w == 0) rsum[i] = 1.f / tot;
    }

    // phase 3: O[d][i] = sum_j V[d][j] * St[j][i], j split across thread halves
    int jh = t >> 7;
    int dq = (t >> 3) & 15;
    int iq = t & 7;
    int dd0 = dq * 4, ic0 = iq * 4;
    float4 o4[4];
#pragma unroll
    for (int u = 0; u < 4; u++) o4[u] = make_float4(0.f, 0.f, 0.f, 0.f);

    for (int jt = 0; jt < 16; jt++) {
        __syncthreads();
#pragma unroll
        for (int p = 0; p < 4; p++) {
            int id = p * 256 + t, d = id >> 4, j4 = (id & 15) * 4;
            *(float4*)&KV[d * KVR + j4] = *(const float4*)&vb[(long)d * HW + jt * 64 + j4];
        }
        __syncthreads();
#pragma unroll
        for (int j4 = 0; j4 < 8; j4++) {
            int j = jh * 32 + j4 * 4;
            float4 v0 = *(const float4*)&KV[(dd0 + 0) * KVR + j];
            float4 v1 = *(const float4*)&KV[(dd0 + 1) * KVR + j];
            float4 v2 = *(const float4*)&KV[(dd0 + 2) * KVR + j];
            float4 v3 = *(const float4*)&KV[(dd0 + 3) * KVR + j];
            int jb = jt * 64 + j;
            float4 s0 = *(const float4*)&St[(jb + 0) * 32 + ic0];
            float4 s1 = *(const float4*)&St[(jb + 1) * 32 + ic0];
            float4 s2 = *(const float4*)&St[(jb + 2) * 32 + ic0];
            float4 s3 = *(const float4*)&St[(jb + 3) * 32 + ic0];
            fma4(o4[0], v0, s0, s1, s2, s3);
            fma4(o4[1], v1, s0, s1, s2, s3);
            fma4(o4[2], v2, s0, s1, s2, s3);
            fma4(o4[3], v3, s0, s1, s2, s3);
        }
    }

    __syncthreads();
    if (jh == 1) {
#pragma unroll
        for (int u = 0; u < 4; u++) *(float4*)&Qs[(dd0 + u) * 32 + ic0] = o4[u];
    }
    __syncthreads();
    if (jh == 0) {
        float4 rs4 = *(const float4*)&rsum[ic0];
        float* ob = out + ((long)b * 256 + h * 64) * HW + i0;
#pragma unroll
        for (int u = 0; u < 4; u++) {
            float4 p = *(const float4*)&Qs[(dd0 + u) * 32 + ic0];
            float4 w;
            w.x = (o4[u].x + p.x) * rs4.x;
            w.y = (o4[u].y + p.y) * rs4.y;
            w.z = (o4[u].z + p.z) * rs4.z;
            w.w = (o4[u].w + p.w) * rs4.w;
            *(float4*)&ob[(long)(dd0 + u) * HW + ic0] = w;
        }
    }
}

// ---------------- launch ----------------
extern "C" void kernel_launch(void* const* d_in, const int* in_sizes, int n_in,
                              void* d_out, int out_size) {
    const float* x       = (const float*)d_in[0];
    const float* cv1_w   = (const float*)d_in[1];
    const float* cv1_bn  = (const float*)d_in[2];
    const float* cv2_w   = (const float*)d_in[3];
    const float* cv2_bn  = (const float*)d_in[4];
    const float* mcv1_w  = (const float*)d_in[5];
    const float* mcv1_bn = (const float*)d_in[6];
    const float* mqkv_w  = (const float*)d_in[7];
    const float* mrw     = (const float*)d_in[8];
    const float* mrh     = (const float*)d_in[9];
    const float* mcv2_w  = (const float*)d_in[10];
    const float* mcv2_bn = (const float*)d_in[11];
    float* out = (float*)d_out;

    cudaFuncSetAttribute(attn_kernel, cudaFuncAttributeMaxDynamicSharedMemorySize, 157824);

    float *cat, *z, *qkv, *att, *scale, *shift;
    cudaGetSymbolAddress((void**)&cat, g_cat);
    cudaGetSymbolAddress((void**)&z, g_z);
    cudaGetSymbolAddress((void**)&qkv, g_qkv);
    cudaGetSymbolAddress((void**)&att, g_att);
    cudaGetSymbolAddress((void**)&scale, g_scale);
    cudaGetSymbolAddress((void**)&shift, g_shift);

    bn_prep<<<8, 256>>>(cv1_bn, cv2_bn, mcv1_bn, mcv2_bn);

    // cv1: [512,512] GEMM -> cat channels [0,512)
    gemm1x1<0><<<dim3(8, 8, 8), 256>>>(x, 512L * HW, cv1_w, 512,
                                       cat, (long)CATC * HW, 0,
                                       scale + 0, shift + 0, nullptr, 0, nullptr, nullptr);

    for (int i = 0; i < 2; i++) {
        const float* yi = cat + (long)(256 + i * 256) * HW;  // + b*CATC*HW inside kernels
        // 3x3 conv + BN + SiLU
        conv3x3<<<dim3(8, 4, 8), 256>>>(yi, (long)CATC * HW,
                                        mcv1_w + (long)i * 256 * 2304, z,
                                        scale + 1024 + i * 256, shift + 1024 + i * 256);
        // qkv 1x1 (q*=0.125, k+=r)
        gemm1x1<2><<<dim3(8, 12, 8), 256>>>(z, 256L * HW, mqkv_w + (long)i * 768 * 256, 256,
                                            qkv, 768L * HW, 0,
                                            nullptr, nullptr, nullptr, 0,
                                            mrw + i * 8192, mrh + i * 8192);
        // attention
        attn_kernel<<<dim3(32, 32), 256, 157824>>>(qkv, att);
        // m_cv2 1x1 + BN + SiLU + residual, written into cat channels [512+i*256, ...)
        gemm1x1<1><<<dim3(8, 4, 8), 256>>>(att, 256L * HW, mcv2_w + (long)i * 256 * 256, 256,
                                           cat, (long)CATC * HW, 512 + i * 256,
                                           scale + 1536 + i * 256, shift + 1536 + i * 256,
                                           yi, (long)CATC * HW, nullptr, nullptr);
    }

    // cv2: [512,1024] GEMM -> output
    gemm1x1<0><<<dim3(8, 8, 8), 256>>>(cat, (long)CATC * HW, cv2_w, 1024,
                                       out, 512L * HW, 0,
                                       scale + 512, shift + 512, nullptr, 0, nullptr, nullptr);
}

// round 4
// speedup vs baseline: 2.0910x; 2.0910x over previous
#include <cuda_runtime.h>
#include <math.h>

#define BB 8
#define HW 1024
#define CCH 256
#define CATC 1024

// ---------------- scratch (no allocations allowed) ----------------
__device__ float g_cat[BB * CATC * HW];        // 32 MB concat buffer [b][1024][1024]
__device__ float g_z[BB * CCH * HW];           // 3x3 conv output
__device__ float g_qkv[BB * 3 * CCH * HW];     // qkv conv output (tf32-rounded)
__device__ float g_att[BB * CCH * HW];         // attention output
__device__ float g_scale[2048];
__device__ float g_shift[2048];
// scale/shift offsets: cv1=0(512), cv2=512(512), mcv1=1024(+i*256), mcv2=1536(+i*256)

__device__ __forceinline__ float silu_f(float x) { return x / (1.f + __expf(-x)); }
__device__ __forceinline__ float to_tf32(float x) {
    float r; asm("cvt.rna.tf32.f32 %0, %1;" : "=f"(r) : "f"(x)); return r;
}
__device__ __forceinline__ unsigned f2u(float x) { return __float_as_uint(x); }

__device__ __forceinline__ void mma_tf32(float acc[4],
                                         unsigned a0, unsigned a1, unsigned a2, unsigned a3,
                                         unsigned b0, unsigned b1) {
    asm volatile(
        "mma.sync.aligned.m16n8k8.row.col.f32.tf32.tf32.f32 "
        "{%0,%1,%2,%3}, {%4,%5,%6,%7}, {%8,%9}, {%0,%1,%2,%3};\n"
        : "+f"(acc[0]), "+f"(acc[1]), "+f"(acc[2]), "+f"(acc[3])
        : "r"(a0), "r"(a1), "r"(a2), "r"(a3), "r"(b0), "r"(b1));
}

// ---------------- BN fold ----------------
__global__ void bn_prep(const float* __restrict__ cv1, const float* __restrict__ cv2,
                        const float* __restrict__ m1, const float* __restrict__ m2) {
    int tid = blockIdx.x * 256 + threadIdx.x;
    if (tid >= 2048) return;
    const float* p; int c; int cc;
    if (tid < 512)       { p = cv1; c = tid;        cc = 512; }
    else if (tid < 1024) { p = cv2; c = tid - 512;  cc = 512; }
    else if (tid < 1536) { int j = tid - 1024; p = m1 + (j >> 8) * 1024; c = j & 255; cc = 256; }
    else                 { int j = tid - 1536; p = m2 + (j >> 8) * 1024; c = j & 255; cc = 256; }
    float g = p[c], bb = p[cc + c], mm = p[2 * cc + c], vv = p[3 * cc + c];
    float s = g * rsqrtf(vv + 1e-3f);
    g_scale[tid] = s;
    g_shift[tid] = bb - mm * s;
}

// ---------------- tf32 GEMM: O[co][m] = sum_k W[co][k] X[k][m] ----------------
// block: 256 thr = 8 warps (4 co-warps x 2 m-warps); tile co=128, m=128, BK=16
// EPI 0: BN+SiLU   EPI 1: BN+SiLU+residual   EPI 2: qkv (q*=0.125, k+=rw+rh, cvt tf32)
#define WS_STR 20
#define XS_STR 136
template <int EPI>
__global__ void __launch_bounds__(256) gemm_tf32(
        const float* __restrict__ X, long xBS,
        const float* __restrict__ W, int Cin,
        float* __restrict__ out, long outBS, int coOff,
        const float* __restrict__ scale, const float* __restrict__ shift,
        const float* __restrict__ res, long resBS,
        const float* __restrict__ rw, const float* __restrict__ rh) {
    __shared__ float Ws[128 * WS_STR];
    __shared__ float Xs[16 * XS_STR];
    int t = threadIdx.x, lane = t & 31, warp = t >> 5;
    int wco = warp & 3, wm = warp >> 2;
    int gid = lane >> 2, tig = lane & 3;
    int m0 = blockIdx.x * 128, n0 = blockIdx.y * 128, b = blockIdx.z;
    const float* Xb = X + (long)b * xBS + m0;

    float acc[2][8][4];
#pragma unroll
    for (int f = 0; f < 2; f++)
#pragma unroll
        for (int g = 0; g < 8; g++)
#pragma unroll
            for (int e = 0; e < 4; e++) acc[f][g][e] = 0.f;

    for (int k0 = 0; k0 < Cin; k0 += 16) {
#pragma unroll
        for (int p = 0; p < 2; p++) {            // W: 128 co x 16 k
            int id = p * 256 + t, co = id >> 2, k4 = (id & 3) * 4;
            float4 w4 = *(const float4*)&W[(long)(n0 + co) * Cin + k0 + k4];
            Ws[co * WS_STR + k4 + 0] = to_tf32(w4.x);
            Ws[co * WS_STR + k4 + 1] = to_tf32(w4.y);
            Ws[co * WS_STR + k4 + 2] = to_tf32(w4.z);
            Ws[co * WS_STR + k4 + 3] = to_tf32(w4.w);
        }
#pragma unroll
        for (int p = 0; p < 2; p++) {            // X: 16 k x 128 m
            int id = p * 256 + t, kk = id >> 5, m4 = (id & 31) * 4;
            float4 x4 = *(const float4*)&Xb[(long)(k0 + kk) * HW + m4];
            float4 c4 = make_float4(to_tf32(x4.x), to_tf32(x4.y), to_tf32(x4.z), to_tf32(x4.w));
            *(float4*)&Xs[kk * XS_STR + m4] = c4;
        }
        __syncthreads();
#pragma unroll
        for (int ks = 0; ks < 2; ks++) {
            int kk0 = ks * 8;
            unsigned a[2][4];
#pragma unroll
            for (int f = 0; f < 2; f++) {
                int cr = wco * 32 + f * 16;
                a[f][0] = f2u(Ws[(cr + gid) * WS_STR + kk0 + tig]);
                a[f][1] = f2u(Ws[(cr + gid + 8) * WS_STR + kk0 + tig]);
                a[f][2] = f2u(Ws[(cr + gid) * WS_STR + kk0 + tig + 4]);
                a[f][3] = f2u(Ws[(cr + gid + 8) * WS_STR + kk0 + tig + 4]);
            }
#pragma unroll
            for (int g = 0; g < 8; g++) {
                int mc = wm * 64 + g * 8 + gid;
                unsigned b0 = f2u(Xs[(kk0 + tig) * XS_STR + mc]);
                unsigned b1 = f2u(Xs[(kk0 + tig + 4) * XS_STR + mc]);
                mma_tf32(acc[0][g], a[0][0], a[0][1], a[0][2], a[0][3], b0, b1);
                mma_tf32(acc[1][g], a[1][0], a[1][1], a[1][2], a[1][3], b0, b1);
            }
        }
        __syncthreads();
    }

    // epilogue
#pragma unroll
    for (int f = 0; f < 2; f++) {
#pragma unroll
        for (int r = 0; r < 2; r++) {
            int col = n0 + wco * 32 + f * 16 + gid + r * 8;
            float s = 0.f, sh = 0.f;
            if (EPI < 2) { s = scale[col]; sh = shift[col]; }
            float* orow = out + (long)b * outBS + (long)(coOff + col) * HW + m0;
            const float* rrow = (EPI == 1) ? res + (long)b * resBS + (long)col * HW + m0 : nullptr;
#pragma unroll
            for (int g = 0; g < 8; g++) {
                int ml = wm * 64 + g * 8 + tig * 2;
                float v0 = acc[f][g][r * 2], v1 = acc[f][g][r * 2 + 1];
                if (EPI < 2) {
                    v0 = silu_f(v0 * s + sh);
                    v1 = silu_f(v1 * s + sh);
                    if (EPI == 1) { v0 += rrow[ml]; v1 += rrow[ml + 1]; }
                } else {
                    int part = col >> 8, cr = col & 255;
                    int m = m0 + ml;
                    if (part == 0) { v0 *= 0.125f; v1 *= 0.125f; }
                    else if (part == 1) {
                        v0 += rw[cr * 32 + (m & 31)] + rh[cr * 32 + (m >> 5)];
                        v1 += rw[cr * 32 + ((m + 1) & 31)] + rh[cr * 32 + ((m + 1) >> 5)];
                    }
                    v0 = to_tf32(v0); v1 = to_tf32(v1);
                }
                *(float2*)&orow[ml] = make_float2(v0, v1);
            }
        }
    }
}

// ---------------- 3x3 conv, tf32 implicit GEMM (K = 2304) ----------------
__global__ void __launch_bounds__(256) conv3x3_tf32(
        const float* __restrict__ X, long xBS,
        const float* __restrict__ W,
        float* __restrict__ out,
        const float* __restrict__ scale, const float* __restrict__ shift) {
    __shared__ float Ws[128 * WS_STR];
    __shared__ float Xs[16 * XS_STR];
    int t = threadIdx.x, lane = t & 31, warp = t >> 5;
    int wco = warp & 3, wm = warp >> 2;
    int gid = lane >> 2, tig = lane & 3;
    int m0 = blockIdx.x * 128, n0 = blockIdx.y * 128, b = blockIdx.z;
    const float* Xb = X + (long)b * xBS;

    float acc[2][8][4];
#pragma unroll
    for (int f = 0; f < 2; f++)
#pragma unroll
        for (int g = 0; g < 8; g++)
#pragma unroll
            for (int e = 0; e < 4; e++) acc[f][g][e] = 0.f;

    for (int k0 = 0; k0 < 2304; k0 += 16) {
#pragma unroll
        for (int p = 0; p < 2; p++) {            // W
            int id = p * 256 + t, co = id >> 2, k4 = (id & 3) * 4;
            float4 w4 = *(const float4*)&W[(long)(n0 + co) * 2304 + k0 + k4];
            Ws[co * WS_STR + k4 + 0] = to_tf32(w4.x);
            Ws[co * WS_STR + k4 + 1] = to_tf32(w4.y);
            Ws[co * WS_STR + k4 + 2] = to_tf32(w4.z);
            Ws[co * WS_STR + k4 + 3] = to_tf32(w4.w);
        }
#pragma unroll
        for (int p = 0; p < 8; p++) {            // X im2col gather
            int id = p * 256 + t, kk = id >> 7, mm = id & 127;
            int kg = k0 + kk;
            int ci = kg / 9, rs = kg - ci * 9;
            int r3 = rs / 3;
            int dr = r3 - 1, ds = rs - r3 * 3 - 1;
            int m = m0 + mm;
            int hh = (m >> 5) + dr, ww = (m & 31) + ds;
            float v = 0.f;
            if ((unsigned)hh < 32u && (unsigned)ww < 32u)
                v = Xb[(long)ci * HW + hh * 32 + ww];
            Xs[kk * XS_STR + mm] = to_tf32(v);
        }
        __syncthreads();
#pragma unroll
        for (int ks = 0; ks < 2; ks++) {
            int kk0 = ks * 8;
            unsigned a[2][4];
#pragma unroll
            for (int f = 0; f < 2; f++) {
                int cr = wco * 32 + f * 16;
                a[f][0] = f2u(Ws[(cr + gid) * WS_STR + kk0 + tig]);
                a[f][1] = f2u(Ws[(cr + gid + 8) * WS_STR + kk0 + tig]);
                a[f][2] = f2u(Ws[(cr + gid) * WS_STR + kk0 + tig + 4]);
                a[f][3] = f2u(Ws[(cr + gid + 8) * WS_STR + kk0 + tig + 4]);
            }
#pragma unroll
            for (int g = 0; g < 8; g++) {
                int mc = wm * 64 + g * 8 + gid;
                unsigned b0 = f2u(Xs[(kk0 + tig) * XS_STR + mc]);
                unsigned b1 = f2u(Xs[(kk0 + tig + 4) * XS_STR + mc]);
                mma_tf32(acc[0][g], a[0][0], a[0][1], a[0][2], a[0][3], b0, b1);
                mma_tf32(acc[1][g], a[1][0], a[1][1], a[1][2], a[1][3], b0, b1);
            }
        }
        __syncthreads();
    }

#pragma unroll
    for (int f = 0; f < 2; f++) {
#pragma unroll
        for (int r = 0; r < 2; r++) {
            int col = n0 + wco * 32 + f * 16 + gid + r * 8;
            float s = scale[col], sh = shift[col];
            float* orow = out + ((long)b * 256 + col) * HW + m0;
#pragma unroll
            for (int g = 0; g < 8; g++) {
                int ml = wm * 64 + g * 8 + tig * 2;
                float v0 = silu_f(acc[f][g][r * 2] * s + sh);
                float v1 = silu_f(acc[f][g][r * 2 + 1] * s + sh);
                *(float2*)&orow[ml] = make_float2(v0, v1);
            }
        }
    }
}

// ---------------- attention (tf32 mma) ----------------
// grid (32 i-tiles, 32 b*h); block 256 (8 warps)
// phase1: S[i][j] = Q^T K'  via mma (M=i, N=j, K=d), stored St[j][i] stride 34
// phase2: softmax over j (exp stored tf32)
// phase3: O[d][i] = V @ P    via mma (M=d, N=i, K=j)
#define QT_STR 72
#define KV_STR 72
#define ST_STR 34
#define ATTN_SMEM ((1024 * ST_STR + 32 * QT_STR + 64 * KV_STR + 256 + 32) * 4)

__global__ void __launch_bounds__(256) attn_tf32(const float* __restrict__ qkv,
                                                 float* __restrict__ out) {
    extern __shared__ float sm[];
    float* St = sm;                        // [1024][34]
    float* Qt = St + 1024 * ST_STR;        // [32][72]  (transposed: [i][d])
    float* KV = Qt + 32 * QT_STR;          // [64][72]  ([d][j])
    float* red = KV + 64 * KV_STR;         // [8][32]
    float* rsum = red + 256;               // [32]

    int t = threadIdx.x, lane = t & 31, warp = t >> 5;
    int gid = lane >> 2, tig = lane & 3;
    int b = blockIdx.y >> 2, h = blockIdx.y & 3;
    int i0 = blockIdx.x * 32;
    const float* qb = qkv + ((long)b * 768 + h * 64) * HW;
    const float* kb = qb + 256 * HW;
    const float* vb = qb + 512 * HW;

    // stage Q transposed: Qt[i][d]  (values already tf32 from qkv epilogue)
#pragma unroll
    for (int p = 0; p < 2; p++) {
        int id = p * 256 + t, d = id >> 3, i4 = (id & 7) * 4;
        float4 q4 = *(const float4*)&qb[(long)d * HW + i0 + i4];
        Qt[(i4 + 0) * QT_STR + d] = q4.x;
        Qt[(i4 + 1) * QT_STR + d] = q4.y;
        Qt[(i4 + 2) * QT_STR + d] = q4.z;
        Qt[(i4 + 3) * QT_STR + d] = q4.w;
    }

    // ---- phase 1: S ----
    int jw = warp & 3, iw = warp >> 2;
    for (int jt = 0; jt < 16; jt++) {
        __syncthreads();
#pragma unroll
        for (int p = 0; p < 4; p++) {
            int id = p * 256 + t, d = id >> 4, j4 = (id & 15) * 4;
            *(float4*)&KV[d * KV_STR + j4] = *(const float4*)&kb[(long)d * HW + jt * 64 + j4];
        }
        __syncthreads();
        float acc[2][4] = {{0.f, 0.f, 0.f, 0.f}, {0.f, 0.f, 0.f, 0.f}};
#pragma unroll
        for (int ks = 0; ks < 8; ks++) {
            int k0 = ks * 8;
            unsigned a0 = f2u(Qt[(iw * 16 + gid) * QT_STR + k0 + tig]);
            unsigned a1 = f2u(Qt[(iw * 16 + gid + 8) * QT_STR + k0 + tig]);
            unsigned a2 = f2u(Qt[(iw * 16 + gid) * QT_STR + k0 + tig + 4]);
            unsigned a3 = f2u(Qt[(iw * 16 + gid + 8) * QT_STR + k0 + tig + 4]);
#pragma unroll
            for (int g = 0; g < 2; g++) {
                int jc = jw * 16 + g * 8;
                unsigned b0 = f2u(KV[(k0 + tig) * KV_STR + jc + gid]);
                unsigned b1 = f2u(KV[(k0 + tig + 4) * KV_STR + jc + gid]);
                mma_tf32(acc[g], a0, a1, a2, a3, b0, b1);
            }
        }
#pragma unroll
        for (int g = 0; g < 2; g++) {
            int j = jt * 64 + jw * 16 + g * 8 + 2 * tig;
            int i = iw * 16 + gid;
            St[j * ST_STR + i] = acc[g][0];
            St[(j + 1) * ST_STR + i] = acc[g][1];
            St[j * ST_STR + i + 8] = acc[g][2];
            St[(j + 1) * ST_STR + i + 8] = acc[g][3];
        }
    }
    __syncthreads();

    // ---- phase 2: softmax over j per column i ----
    {
        int i = t & 31, w = t >> 5;
        float mx = -1e30f;
        for (int j = w; j < 1024; j += 8) mx = fmaxf(mx, St[j * ST_STR + i]);
        red[w * 32 + i] = mx;
        __syncthreads();
        mx = red[i];
#pragma unroll
        for (int u = 1; u < 8; u++) mx = fmaxf(mx, red[u * 32 + i]);
        __syncthreads();
        float s = 0.f;
        for (int j = w; j < 1024; j += 8) {
            float e = to_tf32(__expf(St[j * ST_STR + i] - mx));
            St[j * ST_STR + i] = e;
            s += e;
        }
        red[w * 32 + i] = s;
        __syncthreads();
        float tot = 0.f;
#pragma unroll
        for (int u = 0; u < 8; u++) tot += red[u * 32 + i];
        if (w == 0) rsum[i] = 1.f / tot;
    }

    // ---- phase 3: O = V @ P ----
    int dw = warp & 3, iw3 = warp >> 2;
    float acc3[2][4] = {{0.f, 0.f, 0.f, 0.f}, {0.f, 0.f, 0.f, 0.f}};
    for (int jt = 0; jt < 16; jt++) {
        __syncthreads();
#pragma unroll
        for (int p = 0; p < 4; p++) {
            int id = p * 256 + t, d = id >> 4, j4 = (id & 15) * 4;
            *(float4*)&KV[d * KV_STR + j4] = *(const float4*)&vb[(long)d * HW + jt * 64 + j4];
        }
        __syncthreads();
#pragma unroll
        for (int ks = 0; ks < 8; ks++) {
            int k0 = ks * 8;
            unsigned a0 = f2u(KV[(dw * 16 + gid) * KV_STR + k0 + tig]);
            unsigned a1 = f2u(KV[(dw * 16 + gid + 8) * KV_STR + k0 + tig]);
            unsigned a2 = f2u(KV[(dw * 16 + gid) * KV_STR + k0 + tig + 4]);
            unsigned a3 = f2u(KV[(dw * 16 + gid + 8) * KV_STR + k0 + tig + 4]);
            int jr = jt * 64 + k0;
#pragma unroll
            for (int g = 0; g < 2; g++) {
                int ic = iw3 * 16 + g * 8;
                unsigned b0 = f2u(St[(jr + tig) * ST_STR + ic + gid]);
                unsigned b1 = f2u(St[(jr + tig + 4) * ST_STR + ic + gid]);
                mma_tf32(acc3[g], a0, a1, a2, a3, b0, b1);
            }
        }
    }

    {
        float* ob = out + ((long)b * 256 + h * 64) * HW + i0;
#pragma unroll
        for (int g = 0; g < 2; g++) {
            int ic = iw3 * 16 + g * 8 + 2 * tig;
            float r0 = rsum[ic], r1 = rsum[ic + 1];
            int d0 = dw * 16 + gid;
            *(float2*)&ob[(long)d0 * HW + ic] = make_float2(acc3[g][0] * r0, acc3[g][1] * r1);
            *(float2*)&ob[(long)(d0 + 8) * HW + ic] = make_float2(acc3[g][2] * r0, acc3[g][3] * r1);
        }
    }
}

// ---------------- launch ----------------
extern "C" void kernel_launch(void* const* d_in, const int* in_sizes, int n_in,
                              void* d_out, int out_size) {
    const float* x       = (const float*)d_in[0];
    const float* cv1_w   = (const float*)d_in[1];
    const float* cv1_bn  = (const float*)d_in[2];
    const float* cv2_w   = (const float*)d_in[3];
    const float* cv2_bn  = (const float*)d_in[4];
    const float* mcv1_w  = (const float*)d_in[5];
    const float* mcv1_bn = (const float*)d_in[6];
    const float* mqkv_w  = (const float*)d_in[7];
    const float* mrw     = (const float*)d_in[8];
    const float* mrh     = (const float*)d_in[9];
    const float* mcv2_w  = (const float*)d_in[10];
    const float* mcv2_bn = (const float*)d_in[11];
    float* out = (float*)d_out;

    cudaFuncSetAttribute(attn_tf32, cudaFuncAttributeMaxDynamicSharedMemorySize, ATTN_SMEM);

    float *cat, *z, *qkv, *att, *scale, *shift;
    cudaGetSymbolAddress((void**)&cat, g_cat);
    cudaGetSymbolAddress((void**)&z, g_z);
    cudaGetSymbolAddress((void**)&qkv, g_qkv);
    cudaGetSymbolAddress((void**)&att, g_att);
    cudaGetSymbolAddress((void**)&scale, g_scale);
    cudaGetSymbolAddress((void**)&shift, g_shift);

    bn_prep<<<8, 256>>>(cv1_bn, cv2_bn, mcv1_bn, mcv2_bn);

    // cv1: co=512, Cin=512 -> cat channels [0,512)
    gemm_tf32<0><<<dim3(8, 4, 8), 256>>>(x, 512L * HW, cv1_w, 512,
                                         cat, (long)CATC * HW, 0,
                                         scale + 0, shift + 0, nullptr, 0, nullptr, nullptr);

    for (int i = 0; i < 2; i++) {
        const float* yi = cat + (long)(256 + i * 256) * HW;
        // 3x3 conv + BN + SiLU  (co=256 -> grid.y=2)
        conv3x3_tf32<<<dim3(8, 2, 8), 256>>>(yi, (long)CATC * HW,
                                             mcv1_w + (long)i * 256 * 2304, z,
                                             scale + 1024 + i * 256, shift + 1024 + i * 256);
        // qkv 1x1 (co=768)
        gemm_tf32<2><<<dim3(8, 6, 8), 256>>>(z, 256L * HW, mqkv_w + (long)i * 768 * 256, 256,
                                             qkv, 768L * HW, 0,
                                             nullptr, nullptr, nullptr, 0,
                                             mrw + i * 8192, mrh + i * 8192);
        // attention
        attn_tf32<<<dim3(32, 32), 256, ATTN_SMEM>>>(qkv, att);
        // m_cv2 1x1 + BN + SiLU + residual -> cat channels [512+i*256, ...)
        gemm_tf32<1><<<dim3(8, 2, 8), 256>>>(att, 256L * HW, mcv2_w + (long)i * 256 * 256, 256,
                                             cat, (long)CATC * HW, 512 + i * 256,
                                             scale + 1536 + i * 256, shift + 1536 + i * 256,
                                             yi, (long)CATC * HW, nullptr, nullptr);
    }

    // cv2: co=512, Cin=1024
    gemm_tf32<0><<<dim3(8, 4, 8), 256>>>(cat, (long)CATC * HW, cv2_w, 1024,
                                         out, 512L * HW, 0,
                                         scale + 512, shift + 512, nullptr, 0, nullptr, nullptr);
}